// round 5
// baseline (speedup 1.0000x reference)
#include <cuda_runtime.h>
#include <cuda.h>
#include <cstdint>

// ---------------- cluster kernel constants ----------------
#define TT    9
#define BB    8
#define CC    256
#define HWHW  3136
#define PIX   16           // pixels per cluster tile
#define CHALF 128          // channels per CTA (cluster rank)
#define NTHREADS 512
#define NT    7            // tiles per cluster
#define TILES_PER_B 196    // 3136/16
#define CHUNKS_PER_B 28    // 196/7
#define NBLOCKS 448        // 224 clusters * 2

#define TILE_FLOATS (TT*CHALF*PIX)     // 18432 floats = 73728 B
#define TILE_BYTES  (TILE_FLOATS*4)

// SMEM layout (float offsets)
#define OFF_BUF0  0
#define OFF_BUF1  (TILE_FLOATS)              // 18432
#define OFF_WC    (2*TILE_FLOATS)            // 36864  [CHALF]
#define OFF_WO    (OFF_WC + CHALF)           // 36992  [CHALF]
#define OFF_PART  (OFF_WO + CHALF)           // 37120  [16 warps][160]
#define OFF_SCL   (OFF_PART + 16*160)        // 39680  [160] local scores
#define OFF_SCR   (OFF_SCL + 160)            // 39840  [2][160] remote scores
#define OFF_MBAR  (OFF_SCR + 320)            // 40160  4 x u64 (8B aligned)
#define SMEM_FLOATS (OFF_MBAR + 8)
#define SMEM_BYTES  (SMEM_FLOATS * 4)        // 160704 B

// ---------------- PTX helpers ----------------
#define MBAR_INIT(addr, cnt) \
    asm volatile("mbarrier.init.shared.b64 [%0], %1;" :: "r"(addr), "r"(cnt) : "memory")
#define MBAR_EXPECT_TX(addr, bytes) \
    asm volatile("mbarrier.arrive.expect_tx.shared.b64 _, [%0], %1;" :: "r"(addr), "r"(bytes) : "memory")
#define MBAR_WAIT(addr, parity) do {                                           \
    asm volatile("{\n\t.reg .pred P;\n\t"                                      \
        "WL_%=:\n\t"                                                           \
        "mbarrier.try_wait.parity.acquire.cta.shared::cta.b64 P, [%0], %1, 0x989680;\n\t" \
        "@P bra WD_%=;\n\t"                                                    \
        "bra WL_%=;\n\t"                                                       \
        "WD_%=:\n\t}"                                                          \
        :: "r"(addr), "r"(parity) : "memory");                                 \
} while (0)
#define MBAR_WAIT_CLU(addr, parity) do {                                       \
    asm volatile("{\n\t.reg .pred P;\n\t"                                      \
        "WL_%=:\n\t"                                                           \
        "mbarrier.try_wait.parity.acquire.cluster.shared::cta.b64 P, [%0], %1, 0x989680;\n\t" \
        "@P bra WD_%=;\n\t"                                                    \
        "bra WL_%=;\n\t"                                                       \
        "WD_%=:\n\t}"                                                          \
        :: "r"(addr), "r"(parity) : "memory");                                 \
} while (0)
#define CLUSTER_SYNC() do {                                          \
    asm volatile("barrier.cluster.arrive.aligned;" ::: "memory");    \
    asm volatile("barrier.cluster.wait.aligned;"   ::: "memory");    \
} while (0)

__device__ __forceinline__ uint32_t mapa_peer(uint32_t local_addr, uint32_t peer_rank)
{
    uint32_t r;
    asm("mapa.shared::cluster.u32 %0, %1, %2;" : "=r"(r) : "r"(local_addr), "r"(peer_rank));
    return r;
}

__device__ __forceinline__ void tma_load_tile(uint32_t dst, const CUtensorMap* map,
                                              int x, int y, int z, uint32_t mbar)
{
    asm volatile(
        "cp.async.bulk.tensor.4d.shared::cta.global.tile.mbarrier::complete_tx::bytes "
        "[%0], [%1, {%2, %3, %4, %5}], [%6];"
        :: "r"(dst), "l"(map), "r"(x), "r"(y), "r"(z), "r"(0), "r"(mbar)
        : "memory");
}

// ---------------- cluster kernel ----------------
__global__ __launch_bounds__(NTHREADS, 1) __cluster_dims__(2, 1, 1)
void tfma_clu_kernel(const __grid_constant__ CUtensorMap tmap,
                     const float* __restrict__ wptr,
                     const float* __restrict__ bptr,
                     const float* __restrict__ gptr,
                     float* __restrict__ out)
{
    extern __shared__ float sm[];
    float* wc   = sm + OFF_WC;
    float* wo   = sm + OFF_WO;
    float* part = sm + OFF_PART;
    float* scl  = sm + OFF_SCL;
    float* scr  = sm + OFF_SCR;
    const uint32_t smem_base = (uint32_t)__cvta_generic_to_shared(sm);
    const uint32_t tmbar0 = smem_base + OFF_MBAR * 4;
    const uint32_t tmbar1 = tmbar0 + 8;
    const uint32_t smbar0 = tmbar0 + 16;
    const uint32_t smbar1 = tmbar0 + 24;

    const int tid  = threadIdx.x;
    const int lane = tid & 31;
    const int wrp  = tid >> 5;
    const int p    = tid & (PIX - 1);       // 0..15
    const int cg   = tid >> 4;              // 0..31

    uint32_t rank;
    asm("mov.u32 %0, %%cluster_ctarank;" : "=r"(rank));
    const uint32_t prank = rank ^ 1u;

    const int cid     = blockIdx.x >> 1;          // cluster id 0..223
    const int bidx    = cid / CHUNKS_PER_B;
    const int chunk   = cid % CHUNKS_PER_B;
    const int pixbase = chunk * NT * PIX;
    const int c0      = (int)rank * CHALF;

    if (tid < CHALF) {
        wc[tid] = wptr[c0 + tid];
        wo[tid] = wptr[CC + c0 + tid];
    }
    if (tid == 0) {
        MBAR_INIT(tmbar0, 1);
        MBAR_INIT(tmbar1, 1);
        MBAR_INIT(smbar0, 160);
        MBAR_INIT(smbar1, 160);
    }
    __syncthreads();
    CLUSTER_SYNC();          // all mbars live before any remote traffic

    // prologue: tiles 0 and 1
    if (tid == 0) {
        MBAR_EXPECT_TX(tmbar0, TILE_BYTES);
        tma_load_tile(smem_base + OFF_BUF0 * 4, &tmap, pixbase, c0, bidx, tmbar0);
        MBAR_EXPECT_TX(tmbar1, TILE_BYTES);
        tma_load_tile(smem_base + OFF_BUF1 * 4, &tmap, pixbase + PIX, c0, bidx, tmbar1);
    }

    const float bv    = bptr[0];
    const float gamma = gptr[0];
    float* obase = out + (size_t)bidx * CC * HWHW + (size_t)c0 * HWHW;

    #pragma unroll 1
    for (int k = 0; k < NT; ++k) {
        const int ph = (k >> 1) & 1;
        MBAR_WAIT((k & 1) ? tmbar1 : tmbar0, ph);

        const float* tile = sm + ((k & 1) ? OFF_BUF1 : OFF_BUF0);
        const int pix0 = pixbase + k * PIX;

        // ---- phase 2: pull slice to registers, score partials ----
        float rv[4][TT];
        float acc[TT];
        float accc = 0.f;
        #pragma unroll
        for (int t = 0; t < TT; ++t) acc[t] = 0.f;

        #pragma unroll
        for (int ci = 0; ci < 4; ++ci) {
            const int c = cg + (ci << 5);          // 0..127
            const float wot = wo[c];
            const float wct = wc[c];
            #pragma unroll
            for (int t = 0; t < TT; ++t) {
                rv[ci][t] = tile[(t * CHALF + c) * PIX + p];
                acc[t] = fmaf(rv[ci][t], wot, acc[t]);
                if (t == TT / 2) accc = fmaf(rv[ci][t], wct, accc);
            }
        }
        // warp holds cg pairs (lane^16 = other cg, same p)
        #pragma unroll
        for (int t = 0; t < TT; ++t)
            acc[t] += __shfl_xor_sync(0xffffffffu, acc[t], 16);
        accc += __shfl_xor_sync(0xffffffffu, accc, 16);
        if (lane < PIX) {
            #pragma unroll
            for (int t = 0; t < TT; ++t)
                part[wrp * 160 + t * PIX + lane] = acc[t];
            part[wrp * 160 + TT * PIX + lane] = accc;
        }
        __syncthreads();      // tile fully consumed; partials visible

        // ---- refill the just-consumed buffer with tile k+2 ----
        if (k + 2 < NT && tid == 0) {
            const uint32_t mb  = (k & 1) ? tmbar1 : tmbar0;
            const uint32_t dst = smem_base + ((k & 1) ? OFF_BUF1 : OFF_BUF0) * 4;
            MBAR_EXPECT_TX(mb, TILE_BYTES);
            tma_load_tile(dst, &tmap, pixbase + (k + 2) * PIX, c0, bidx, mb);
        }

        // ---- cross-warp reduce + exchange halves with peer ----
        if (tid < 160) {
            float s = 0.f;
            #pragma unroll
            for (int g = 0; g < 16; ++g) s += part[g * 160 + tid];
            scl[tid] = s;
            // push to peer's scr[k&1][tid]
            const uint32_t myrem = smem_base + (OFF_SCR + (k & 1) * 160 + tid) * 4;
            const uint32_t prem  = mapa_peer(myrem, prank);
            asm volatile("st.shared::cluster.b32 [%0], %1;"
                         :: "r"(prem), "r"(__float_as_uint(s)) : "memory");
            const uint32_t pmbar = mapa_peer((k & 1) ? smbar1 : smbar0, prank);
            asm volatile("mbarrier.arrive.release.cluster.shared::cluster.b64 _, [%0];"
                         :: "r"(pmbar) : "memory");
        }
        __syncthreads();                           // scl visible CTA-wide
        MBAR_WAIT_CLU((k & 1) ? smbar1 : smbar0, ph);   // peer half arrived

        // ---- phase 3: softmax + attended sum from registers ----
        {
            const float* sr = scr + (k & 1) * 160;
            const float centv = scl[TT * PIX + p] + sr[TT * PIX + p];
            float a[TT];
            float m = -1e30f;
            #pragma unroll
            for (int t = 0; t < TT; ++t) {
                a[t] = scl[t * PIX + p] + sr[t * PIX + p] + centv + bv;
                m = fmaxf(m, a[t]);
            }
            float sum = 0.f;
            #pragma unroll
            for (int t = 0; t < TT; ++t) {
                a[t] = __expf(a[t] - m);
                sum += a[t];
            }
            const float inv = 1.f / sum;
            #pragma unroll
            for (int t = 0; t < TT; ++t) a[t] *= inv;

            float* ob = obase + pix0 + p;
            #pragma unroll
            for (int ci = 0; ci < 4; ++ci) {
                const int c = cg + (ci << 5);
                float s = 0.f;
                #pragma unroll
                for (int t = 0; t < TT; ++t)
                    s = fmaf(a[t], rv[ci][t], s);
                ob[(size_t)c * HWHW] = rv[ci][TT / 2] + gamma * s;
            }
        }
    }

    CLUSTER_SYNC();   // peer may still be writing into our scr/mbars
}

// ---------------- fallback kernel (proven cp.async path, no TMA/cluster) ----
#define FBPIX 8
#define FB_CHUNKS 56
#define FB_TILEF (TT*CC*FBPIX)
#define FB_OFF_WC   (2*FB_TILEF)
#define FB_OFF_WO   (FB_OFF_WC + CC)
#define FB_OFF_PART (FB_OFF_WO + CC)
#define FB_OFF_SCOR (FB_OFF_PART + 16*80)
#define FB_SMEM_BYTES ((FB_OFF_SCOR + 80) * 4)

__device__ __forceinline__ void fb_issue_tile(uint32_t smem_dst_bytes,
                                              const float* __restrict__ src, int tid)
{
    const int q = tid & 1;
    const int c = tid >> 1;
    const float* g = src + (size_t)c * HWHW + q * 4;
    uint32_t s = smem_dst_bytes + (uint32_t)((c * FBPIX + q * 4) * 4);
    #pragma unroll
    for (int t = 0; t < TT; ++t) {
        asm volatile("cp.async.cg.shared.global [%0], [%1], 16;\n"
                     :: "r"(s), "l"(g) : "memory");
        g += (size_t)BB * CC * HWHW;
        s += CC * FBPIX * 4;
    }
}

__global__ __launch_bounds__(NTHREADS, 1)
void tfma_fb_kernel(const float* __restrict__ seq,
                    const float* __restrict__ wptr,
                    const float* __restrict__ bptr,
                    const float* __restrict__ gptr,
                    float* __restrict__ out)
{
    extern __shared__ float sm[];
    float* wc   = sm + FB_OFF_WC;
    float* wo   = sm + FB_OFF_WO;
    float* part = sm + FB_OFF_PART;
    float* scor = sm + FB_OFF_SCOR;
    const uint32_t smem_base = (uint32_t)__cvta_generic_to_shared(sm);

    const int tid  = threadIdx.x;
    const int lane = tid & 31;
    const int wrp  = tid >> 5;
    const int p    = tid & (FBPIX - 1);
    const int cg   = tid >> 3;
    const int bidx  = blockIdx.x / FB_CHUNKS;
    const int chunk = blockIdx.x % FB_CHUNKS;
    const float* tbase = seq + (size_t)bidx * CC * HWHW;

    if (tid < CC) { wc[tid] = wptr[tid]; wo[tid] = wptr[CC + tid]; }

    fb_issue_tile(smem_base, tbase + (size_t)(chunk * NT) * FBPIX, tid);
    asm volatile("cp.async.commit_group;\n" ::: "memory");

    const float bv    = bptr[0];
    const float gamma = gptr[0];
    float* obase0 = out + (size_t)bidx * CC * HWHW;

    for (int k = 0; k < NT; ++k) {
        if (k + 1 < NT)
            fb_issue_tile(smem_base + ((k & 1) ? 0 : FB_TILEF) * 4,
                          tbase + (size_t)((chunk * NT + k + 1) * FBPIX), tid);
        asm volatile("cp.async.commit_group;\n" ::: "memory");
        asm volatile("cp.async.wait_group 1;\n" ::: "memory");
        __syncthreads();

        const float* tile = sm + ((k & 1) ? FB_TILEF : 0);
        const int pix0 = (chunk * NT + k) * FBPIX;

        float rv[4][TT];
        float acc[TT]; float accc = 0.f;
        #pragma unroll
        for (int t = 0; t < TT; ++t) acc[t] = 0.f;
        #pragma unroll
        for (int ci = 0; ci < 4; ++ci) {
            const int c = cg + (ci << 6);
            const float wot = wo[c], wct = wc[c];
            #pragma unroll
            for (int t = 0; t < TT; ++t) {
                rv[ci][t] = tile[(t * CC + c) * FBPIX + p];
                acc[t] = fmaf(rv[ci][t], wot, acc[t]);
                if (t == TT / 2) accc = fmaf(rv[ci][t], wct, accc);
            }
        }
        #pragma unroll
        for (int t = 0; t < TT; ++t) {
            acc[t] += __shfl_xor_sync(0xffffffffu, acc[t], 8);
            acc[t] += __shfl_xor_sync(0xffffffffu, acc[t], 16);
        }
        accc += __shfl_xor_sync(0xffffffffu, accc, 8);
        accc += __shfl_xor_sync(0xffffffffu, accc, 16);
        if (lane < FBPIX) {
            #pragma unroll
            for (int t = 0; t < TT; ++t) part[wrp * 80 + t * FBPIX + lane] = acc[t];
            part[wrp * 80 + TT * FBPIX + lane] = accc;
        }
        __syncthreads();
        if (tid < 80) {
            float s = 0.f;
            #pragma unroll
            for (int g = 0; g < 16; ++g) s += part[g * 80 + tid];
            scor[tid] = s;
        }
        __syncthreads();
        {
            const float centv = scor[TT * FBPIX + p];
            float a[TT]; float m = -1e30f;
            #pragma unroll
            for (int t = 0; t < TT; ++t) { a[t] = scor[t * FBPIX + p] + centv + bv; m = fmaxf(m, a[t]); }
            float sum = 0.f;
            #pragma unroll
            for (int t = 0; t < TT; ++t) { a[t] = __expf(a[t] - m); sum += a[t]; }
            const float inv = 1.f / sum;
            #pragma unroll
            for (int t = 0; t < TT; ++t) a[t] *= inv;

            float* ob = obase0 + pix0 + p;
            #pragma unroll
            for (int ci = 0; ci < 4; ++ci) {
                const int c = cg + (ci << 6);
                float s = 0.f;
                #pragma unroll
                for (int t = 0; t < TT; ++t) s = fmaf(a[t], rv[ci][t], s);
                ob[(size_t)c * HWHW] = rv[ci][TT / 2] + gamma * s;
            }
        }
        __syncthreads();
    }
}

// ---------------- host ----------------
typedef CUresult (*EncodeTiledFn)(CUtensorMap*, CUtensorMapDataType, cuuint32_t, void*,
                                  const cuuint64_t*, const cuuint64_t*,
                                  const cuuint32_t*, const cuuint32_t*,
                                  CUtensorMapInterleave, CUtensorMapSwizzle,
                                  CUtensorMapL2promotion, CUtensorMapFloatOOBfill);

extern "C" void kernel_launch(void* const* d_in, const int* in_sizes, int n_in,
                              void* d_out, int out_size)
{
    (void)in_sizes; (void)n_in; (void)out_size;
    const float* seq   = (const float*)d_in[0];
    const float* w     = (const float*)d_in[1];
    const float* bv    = (const float*)d_in[2];
    const float* gamma = (const float*)d_in[3];
    float* out = (float*)d_out;

    void* fn = nullptr;
    cudaDriverEntryPointQueryResult qr = cudaDriverEntryPointSymbolNotFound;
    cudaGetDriverEntryPointByVersion("cuTensorMapEncodeTiled", &fn, 12000,
                                     cudaEnableDefault, &qr);

    bool tma_ok = false;
    CUtensorMap tmap;
    if (fn && qr == cudaDriverEntryPointSuccess) {
        cuuint64_t dims[4]    = {HWHW, CC, BB, TT};
        cuuint64_t strides[3] = {(cuuint64_t)HWHW * 4,
                                 (cuuint64_t)CC * HWHW * 4,
                                 (cuuint64_t)BB * CC * HWHW * 4};
        cuuint32_t box[4]     = {PIX, CHALF, 1, TT};   // 16 px, 128 ch, 9 t
        cuuint32_t estr[4]    = {1, 1, 1, 1};
        CUresult r = ((EncodeTiledFn)fn)(
            &tmap, CU_TENSOR_MAP_DATA_TYPE_FLOAT32, 4, (void*)seq,
            dims, strides, box, estr,
            CU_TENSOR_MAP_INTERLEAVE_NONE, CU_TENSOR_MAP_SWIZZLE_NONE,
            CU_TENSOR_MAP_L2_PROMOTION_L2_128B, CU_TENSOR_MAP_FLOAT_OOB_FILL_NONE);
        tma_ok = (r == CUDA_SUCCESS);
    }

    if (tma_ok) {
        cudaFuncSetAttribute(tfma_clu_kernel,
                             cudaFuncAttributeMaxDynamicSharedMemorySize, SMEM_BYTES);
        tfma_clu_kernel<<<NBLOCKS, NTHREADS, SMEM_BYTES>>>(tmap, w, bv, gamma, out);
    } else {
        cudaFuncSetAttribute(tfma_fb_kernel,
                             cudaFuncAttributeMaxDynamicSharedMemorySize, FB_SMEM_BYTES);
        tfma_fb_kernel<<<NBLOCKS, NTHREADS, FB_SMEM_BYTES>>>(seq, w, bv, gamma, out);
    }
}

// round 6
// speedup vs baseline: 1.5420x; 1.5420x over previous
#include <cuda_runtime.h>
#include <cuda.h>
#include <cstdint>

// ---------------- constants ----------------
#define TT    9
#define BB    8
#define CC    256
#define HWHW  3136
#define PIX   16
#define NTHREADS 1024
#define TILES_PER_B 196          // 3136/16
#define TILES_TOTAL 1568         // 8*196
#define GRID  148                // persistent, 1 CTA/SM

#define H0_T  4                  // t = 0..3
#define H1_T  5                  // t = 4..8
#define H0_BYTES (H0_T*CC*PIX*4) // 65536
#define H1_BYTES (H1_T*CC*PIX*4) // 81920
#define TILE_FLOATS (TT*CC*PIX)  // 36864 floats = 147456 B

// SMEM layout (float offsets)
#define OFF_TILE 0
#define OFF_PART (TILE_FLOATS)           // [32 warps][160]
#define OFF_SCOR (OFF_PART + 32*160)     // [160]
#define OFF_MBAR (OFF_SCOR + 160)        // 2 x u64 (byte 168576, 8B aligned)
#define SMEM_FLOATS (OFF_MBAR + 4)
#define SMEM_BYTES  (SMEM_FLOATS * 4)    // 168592 B

// ---------------- PTX helpers ----------------
#define MBAR_INIT(addr, cnt) \
    asm volatile("mbarrier.init.shared.b64 [%0], %1;" :: "r"(addr), "r"(cnt) : "memory")
#define MBAR_EXPECT_TX(addr, bytes) \
    asm volatile("mbarrier.arrive.expect_tx.shared.b64 _, [%0], %1;" :: "r"(addr), "r"(bytes) : "memory")
#define MBAR_WAIT(addr, parity) do {                                           \
    asm volatile("{\n\t.reg .pred P;\n\t"                                      \
        "WL_%=:\n\t"                                                           \
        "mbarrier.try_wait.parity.acquire.cta.shared::cta.b64 P, [%0], %1, 0x989680;\n\t" \
        "@P bra WD_%=;\n\t"                                                    \
        "bra WL_%=;\n\t"                                                       \
        "WD_%=:\n\t}"                                                          \
        :: "r"(addr), "r"(parity) : "memory");                                 \
} while (0)

__device__ __forceinline__ void tma_load4d(uint32_t dst, const CUtensorMap* map,
                                           int x, int z, int tw, uint32_t mbar)
{
    asm volatile(
        "cp.async.bulk.tensor.4d.shared::cta.global.tile.mbarrier::complete_tx::bytes "
        "[%0], [%1, {%2, %3, %4, %5}], [%6];"
        :: "r"(dst), "l"(map), "r"(x), "r"(0), "r"(z), "r"(tw), "r"(mbar)
        : "memory");
}

// ---------------- main kernel ----------------
__global__ __launch_bounds__(NTHREADS, 1)
void tfma_p16_kernel(const __grid_constant__ CUtensorMap tmapA,   // box {16,256,1,4}
                     const __grid_constant__ CUtensorMap tmapB,   // box {16,256,1,5}
                     const float* __restrict__ wptr,
                     const float* __restrict__ bptr,
                     const float* __restrict__ gptr,
                     float* __restrict__ out)
{
    extern __shared__ float sm[];
    float* part = sm + OFF_PART;
    float* scor = sm + OFF_SCOR;
    const uint32_t smem_base = (uint32_t)__cvta_generic_to_shared(sm);
    const uint32_t mb0 = smem_base + OFF_MBAR * 4;
    const uint32_t mb1 = mb0 + 8;
    const uint32_t dst0 = smem_base;                    // t = 0..3
    const uint32_t dst1 = smem_base + H0_BYTES;         // t = 4..8

    const int tid  = threadIdx.x;
    const int lane = tid & 31;
    const int wrp  = tid >> 5;
    const int p    = tid & (PIX - 1);   // 0..15
    const int cg   = tid >> 4;          // 0..63

    // static balanced tile range: [bid*392/37, (bid+1)*392/37)
    const int g0   = (int)(((long)blockIdx.x * 392) / 37);
    const int g1   = (int)(((long)(blockIdx.x + 1) * 392) / 37);
    const int cnt  = g1 - g0;
    if (cnt <= 0) return;

    // preload weights to registers (fixed c per thread across all tiles)
    float wct[4], wot[4];
    #pragma unroll
    for (int ci = 0; ci < 4; ++ci) {
        wct[ci] = wptr[cg + (ci << 6)];
        wot[ci] = wptr[CC + cg + (ci << 6)];
    }
    const float bv    = bptr[0];
    const float gamma = gptr[0];

    if (tid == 0) {
        MBAR_INIT(mb0, 1);
        MBAR_INIT(mb1, 1);
    }
    __syncthreads();

    // prologue: both halves of tile g0
    {
        const int bidx = g0 / TILES_PER_B;
        const int pix0 = (g0 % TILES_PER_B) * PIX;
        if (tid == 0) {
            MBAR_EXPECT_TX(mb0, H0_BYTES);
            tma_load4d(dst0, &tmapA, pix0, bidx, 0, mb0);
            MBAR_EXPECT_TX(mb1, H1_BYTES);
            tma_load4d(dst1, &tmapB, pix0, bidx, H0_T, mb1);
        }
    }

    #pragma unroll 1
    for (int k = 0; k < cnt; ++k) {
        const int g    = g0 + k;
        const int bidx = g / TILES_PER_B;
        const int pix0 = (g % TILES_PER_B) * PIX;
        const int ph   = k & 1;

        // next-tile coords (used by mid-iter refills)
        const int gn    = g + 1;
        const int nbidx = gn / TILES_PER_B;
        const int npix0 = (gn % TILES_PER_B) * PIX;
        const bool more = (k + 1 < cnt);

        float rv[4][TT];
        float acc[TT];
        float accc = 0.f;
        #pragma unroll
        for (int t = 0; t < TT; ++t) acc[t] = 0.f;

        // ---- half 0: t = 0..3 ----
        MBAR_WAIT(mb0, ph);
        #pragma unroll
        for (int ci = 0; ci < 4; ++ci) {
            const int c = cg + (ci << 6);
            #pragma unroll
            for (int t = 0; t < H0_T; ++t) {
                rv[ci][t] = sm[(t * CC + c) * PIX + p];
                acc[t] = fmaf(rv[ci][t], wot[ci], acc[t]);
            }
        }
        __syncthreads();                       // half0 consumed by all
        if (more && tid == 0) {
            MBAR_EXPECT_TX(mb0, H0_BYTES);
            tma_load4d(dst0, &tmapA, npix0, nbidx, 0, mb0);
        }

        // ---- half 1: t = 4..8 ----
        MBAR_WAIT(mb1, ph);
        #pragma unroll
        for (int ci = 0; ci < 4; ++ci) {
            const int c = cg + (ci << 6);
            #pragma unroll
            for (int t = H0_T; t < TT; ++t) {
                rv[ci][t] = sm[(t * CC + c) * PIX + p];
                acc[t] = fmaf(rv[ci][t], wot[ci], acc[t]);
            }
            accc = fmaf(rv[ci][TT / 2], wct[ci], accc);
        }
        // warp partials: xor16 combines the warp's two c-groups (same p)
        #pragma unroll
        for (int t = 0; t < TT; ++t)
            acc[t] += __shfl_xor_sync(0xffffffffu, acc[t], 16);
        accc += __shfl_xor_sync(0xffffffffu, accc, 16);
        if (lane < PIX) {
            #pragma unroll
            for (int t = 0; t < TT; ++t)
                part[wrp * 160 + t * PIX + lane] = acc[t];
            part[wrp * 160 + TT * PIX + lane] = accc;
        }
        __syncthreads();                       // half1 consumed, partials visible
        if (more && tid == 0) {
            MBAR_EXPECT_TX(mb1, H1_BYTES);
            tma_load4d(dst1, &tmapB, npix0, nbidx, H0_T, mb1);
        }

        // ---- cross-warp reduce: 160 threads ----
        if (tid < 160) {
            float s = 0.f;
            #pragma unroll
            for (int w = 0; w < 32; ++w) s += part[w * 160 + tid];
            scor[tid] = s;
        }
        __syncthreads();

        // ---- softmax + attended sum + residual (all from registers) ----
        {
            const float centv = scor[TT * PIX + p];
            float a[TT];
            float m = -1e30f;
            #pragma unroll
            for (int t = 0; t < TT; ++t) {
                a[t] = scor[t * PIX + p] + centv + bv;
                m = fmaxf(m, a[t]);
            }
            float sum = 0.f;
            #pragma unroll
            for (int t = 0; t < TT; ++t) {
                a[t] = __expf(a[t] - m);
                sum += a[t];
            }
            const float inv = 1.f / sum;
            #pragma unroll
            for (int t = 0; t < TT; ++t) a[t] *= inv;

            float* ob = out + (size_t)bidx * CC * HWHW + pix0 + p;
            #pragma unroll
            for (int ci = 0; ci < 4; ++ci) {
                const int c = cg + (ci << 6);
                float s = 0.f;
                #pragma unroll
                for (int t = 0; t < TT; ++t)
                    s = fmaf(a[t], rv[ci][t], s);
                ob[(size_t)c * HWHW] = rv[ci][TT / 2] + gamma * s;
            }
        }
        // no trailing barrier: next iter gates on mbar waits; scor/part reuse
        // is protected because their next writes follow barriers that require
        // every thread to have finished this iteration's reads.
    }
}

// ---------------- fallback kernel (proven cp.async path) ----------------
#define FBPIX 8
#define FB_NT 7
#define FB_CHUNKS 56
#define FB_TILEF (TT*CC*FBPIX)
#define FB_OFF_WC   (2*FB_TILEF)
#define FB_OFF_WO   (FB_OFF_WC + CC)
#define FB_OFF_PART (FB_OFF_WO + CC)
#define FB_OFF_SCOR (FB_OFF_PART + 16*80)
#define FB_SMEM_BYTES ((FB_OFF_SCOR + 80) * 4)

__device__ __forceinline__ void fb_issue_tile(uint32_t smem_dst_bytes,
                                              const float* __restrict__ src, int tid)
{
    const int q = tid & 1;
    const int c = tid >> 1;
    const float* g = src + (size_t)c * HWHW + q * 4;
    uint32_t s = smem_dst_bytes + (uint32_t)((c * FBPIX + q * 4) * 4);
    #pragma unroll
    for (int t = 0; t < TT; ++t) {
        asm volatile("cp.async.cg.shared.global [%0], [%1], 16;\n"
                     :: "r"(s), "l"(g) : "memory");
        g += (size_t)BB * CC * HWHW;
        s += CC * FBPIX * 4;
    }
}

__global__ __launch_bounds__(512, 1)
void tfma_fb_kernel(const float* __restrict__ seq,
                    const float* __restrict__ wptr,
                    const float* __restrict__ bptr,
                    const float* __restrict__ gptr,
                    float* __restrict__ out)
{
    extern __shared__ float sm[];
    float* wc   = sm + FB_OFF_WC;
    float* wo   = sm + FB_OFF_WO;
    float* part = sm + FB_OFF_PART;
    float* scor = sm + FB_OFF_SCOR;
    const uint32_t smem_base = (uint32_t)__cvta_generic_to_shared(sm);

    const int tid  = threadIdx.x;
    const int lane = tid & 31;
    const int wrp  = tid >> 5;
    const int p    = tid & (FBPIX - 1);
    const int cg   = tid >> 3;
    const int bidx  = blockIdx.x / FB_CHUNKS;
    const int chunk = blockIdx.x % FB_CHUNKS;
    const float* tbase = seq + (size_t)bidx * CC * HWHW;

    if (tid < CC) { wc[tid] = wptr[tid]; wo[tid] = wptr[CC + tid]; }

    fb_issue_tile(smem_base, tbase + (size_t)(chunk * FB_NT) * FBPIX, tid);
    asm volatile("cp.async.commit_group;\n" ::: "memory");

    const float bv    = bptr[0];
    const float gamma = gptr[0];
    float* obase0 = out + (size_t)bidx * CC * HWHW;

    for (int k = 0; k < FB_NT; ++k) {
        if (k + 1 < FB_NT)
            fb_issue_tile(smem_base + ((k & 1) ? 0 : FB_TILEF) * 4,
                          tbase + (size_t)((chunk * FB_NT + k + 1) * FBPIX), tid);
        asm volatile("cp.async.commit_group;\n" ::: "memory");
        asm volatile("cp.async.wait_group 1;\n" ::: "memory");
        __syncthreads();

        const float* tile = sm + ((k & 1) ? FB_TILEF : 0);
        const int pix0 = (chunk * FB_NT + k) * FBPIX;

        float rv[4][TT];
        float acc[TT]; float accc = 0.f;
        #pragma unroll
        for (int t = 0; t < TT; ++t) acc[t] = 0.f;
        #pragma unroll
        for (int ci = 0; ci < 4; ++ci) {
            const int c = cg + (ci << 6);
            const float wotv = wo[c], wctv = wc[c];
            #pragma unroll
            for (int t = 0; t < TT; ++t) {
                rv[ci][t] = tile[(t * CC + c) * FBPIX + p];
                acc[t] = fmaf(rv[ci][t], wotv, acc[t]);
                if (t == TT / 2) accc = fmaf(rv[ci][t], wctv, accc);
            }
        }
        #pragma unroll
        for (int t = 0; t < TT; ++t) {
            acc[t] += __shfl_xor_sync(0xffffffffu, acc[t], 8);
            acc[t] += __shfl_xor_sync(0xffffffffu, acc[t], 16);
        }
        accc += __shfl_xor_sync(0xffffffffu, accc, 8);
        accc += __shfl_xor_sync(0xffffffffu, accc, 16);
        if (lane < FBPIX) {
            #pragma unroll
            for (int t = 0; t < TT; ++t) part[wrp * 80 + t * FBPIX + lane] = acc[t];
            part[wrp * 80 + TT * FBPIX + lane] = accc;
        }
        __syncthreads();
        if (tid < 80) {
            float s = 0.f;
            #pragma unroll
            for (int g = 0; g < 16; ++g) s += part[g * 80 + tid];
            scor[tid] = s;
        }
        __syncthreads();
        {
            const float centv = scor[TT * FBPIX + p];
            float a[TT]; float m = -1e30f;
            #pragma unroll
            for (int t = 0; t < TT; ++t) { a[t] = scor[t * FBPIX + p] + centv + bv; m = fmaxf(m, a[t]); }
            float sum = 0.f;
            #pragma unroll
            for (int t = 0; t < TT; ++t) { a[t] = __expf(a[t] - m); sum += a[t]; }
            const float inv = 1.f / sum;
            #pragma unroll
            for (int t = 0; t < TT; ++t) a[t] *= inv;

            float* ob = obase0 + pix0 + p;
            #pragma unroll
            for (int ci = 0; ci < 4; ++ci) {
                const int c = cg + (ci << 6);
                float s = 0.f;
                #pragma unroll
                for (int t = 0; t < TT; ++t) s = fmaf(a[t], rv[ci][t], s);
                ob[(size_t)c * HWHW] = rv[ci][TT / 2] + gamma * s;
            }
        }
        __syncthreads();
    }
}

// ---------------- host ----------------
typedef CUresult (*EncodeTiledFn)(CUtensorMap*, CUtensorMapDataType, cuuint32_t, void*,
                                  const cuuint64_t*, const cuuint64_t*,
                                  const cuuint32_t*, const cuuint32_t*,
                                  CUtensorMapInterleave, CUtensorMapSwizzle,
                                  CUtensorMapL2promotion, CUtensorMapFloatOOBfill);

extern "C" void kernel_launch(void* const* d_in, const int* in_sizes, int n_in,
                              void* d_out, int out_size)
{
    (void)in_sizes; (void)n_in; (void)out_size;
    const float* seq   = (const float*)d_in[0];
    const float* w     = (const float*)d_in[1];
    const float* bv    = (const float*)d_in[2];
    const float* gamma = (const float*)d_in[3];
    float* out = (float*)d_out;

    void* fn = nullptr;
    cudaDriverEntryPointQueryResult qr = cudaDriverEntryPointSymbolNotFound;
    cudaGetDriverEntryPointByVersion("cuTensorMapEncodeTiled", &fn, 12000,
                                     cudaEnableDefault, &qr);

    bool tma_ok = false;
    CUtensorMap tmapA, tmapB;
    if (fn && qr == cudaDriverEntryPointSuccess) {
        cuuint64_t dims[4]    = {HWHW, CC, BB, TT};
        cuuint64_t strides[3] = {(cuuint64_t)HWHW * 4,
                                 (cuuint64_t)CC * HWHW * 4,
                                 (cuuint64_t)BB * CC * HWHW * 4};
        cuuint32_t estr[4]    = {1, 1, 1, 1};
        cuuint32_t boxA[4]    = {PIX, CC, 1, H0_T};
        cuuint32_t boxB[4]    = {PIX, CC, 1, H1_T};
        CUresult rA = ((EncodeTiledFn)fn)(
            &tmapA, CU_TENSOR_MAP_DATA_TYPE_FLOAT32, 4, (void*)seq,
            dims, strides, boxA, estr,
            CU_TENSOR_MAP_INTERLEAVE_NONE, CU_TENSOR_MAP_SWIZZLE_NONE,
            CU_TENSOR_MAP_L2_PROMOTION_L2_128B, CU_TENSOR_MAP_FLOAT_OOB_FILL_NONE);
        CUresult rB = ((EncodeTiledFn)fn)(
            &tmapB, CU_TENSOR_MAP_DATA_TYPE_FLOAT32, 4, (void*)seq,
            dims, strides, boxB, estr,
            CU_TENSOR_MAP_INTERLEAVE_NONE, CU_TENSOR_MAP_SWIZZLE_NONE,
            CU_TENSOR_MAP_L2_PROMOTION_L2_128B, CU_TENSOR_MAP_FLOAT_OOB_FILL_NONE);
        tma_ok = (rA == CUDA_SUCCESS && rB == CUDA_SUCCESS);
    }

    if (tma_ok) {
        cudaFuncSetAttribute(tfma_p16_kernel,
                             cudaFuncAttributeMaxDynamicSharedMemorySize, SMEM_BYTES);
        tfma_p16_kernel<<<GRID, NTHREADS, SMEM_BYTES>>>(tmapA, tmapB, w, bv, gamma, out);
    } else {
        cudaFuncSetAttribute(tfma_fb_kernel,
                             cudaFuncAttributeMaxDynamicSharedMemorySize, FB_SMEM_BYTES);
        tfma_fb_kernel<<<448, 512, FB_SMEM_BYTES>>>(seq, w, bv, gamma, out);
    }
}